// round 15
// baseline (speedup 1.0000x reference)
#include <cuda_runtime.h>

// CRF negative log-likelihood, L=64 live states, exp-domain recursion.
// ONE WARP PER BATCH: lane l owns states (2l, 2l+1); v exchanged through
// a per-warp smem buffer with __syncwarp() only — no cross-warp barrier,
// no barrier STS-drain, no arrival skew. Block = 64 = 2 independent warps,
// grid = ceil(B/2) -> 1 CTA/SM, single wave.
//
//   v_t[j]  = (sum_i v_{t-1}[i] * E[i][j]) * exp(pred[b,t-1,j]) * 2^{-ex_t}
//   E[i][j] = exp(trans[i][j]);  ex_t = float exponent of v_{t-1}[0]
//   logZ_b  = m0 + ks*ln2 + log( sum_j v_seq[j] * exp(trans[j][65]) )
//   gold_b  = sum_t pred[b,t,ref_t] + trans[64][ref_0]
//           + sum trans[ref_{t-1}][ref_t] + trans[ref_{seq-1}][65]

__device__ double g_partial[4096];
__device__ int    g_count;   // static zero-init; last CTA resets each run

__device__ __forceinline__ float warp_rmax(float v) {
#pragma unroll
    for (int o = 16; o > 0; o >>= 1)
        v = fmaxf(v, __shfl_xor_sync(0xffffffffu, v, o));
    return v;
}
__device__ __forceinline__ float warp_rsum(float v) {
#pragma unroll
    for (int o = 16; o > 0; o >>= 1)
        v += __shfl_xor_sync(0xffffffffu, v, o);
    return v;
}

typedef unsigned long long u64;
__device__ __forceinline__ u64 ffma2(u64 a, u64 b, u64 c) {
    u64 d;
    asm("fma.rn.f32x2 %0, %1, %2, %3;" : "=l"(d) : "l"(a), "l"(b), "l"(c));
    return d;
}
__device__ __forceinline__ u64 fadd2(u64 a, u64 b) {
    u64 d;
    asm("add.rn.f32x2 %0, %1, %2;" : "=l"(d) : "l"(a), "l"(b));
    return d;
}
__device__ __forceinline__ u64 pack2(float lo, float hi) {
    u64 d;
    asm("mov.b64 %0, {%1, %2};" : "=l"(d) : "f"(lo), "f"(hi));
    return d;
}

__global__ void __launch_bounds__(64)
crf_kernel(const float* __restrict__ pred,
           const float* __restrict__ trans,
           const int*   __restrict__ ref,
           const int*   __restrict__ slen,
           float* __restrict__ out,
           int B, int T, int out_size)
{
    __shared__ float4 ebuf[2][2][16];   // [warp][parity][16] = 64 floats
    __shared__ double red[64];
    __shared__ int    s_last;

    const int tid  = threadIdx.x;
    const int w    = tid >> 5;          // warp 0/1 = independent batch
    const int lane = tid & 31;
    const int j0   = 2 * lane;          // owned states
    const int j1   = 2 * lane + 1;

    const int  breq = blockIdx.x * 2 + w;
    const bool wr   = (breq < B);
    const int  b    = wr ? breq : (B - 1);

    const float* pb  = pred + (size_t)b * T * 64;
    const int*   rb  = ref  + (size_t)b * T;
    const int    seq = slen[b];

    // E columns j0 and j1: 32 packed f32x2 pairs each.
    //   Ea[k] = (E[2k][j0], E[2k+1][j0]),  Eb[k] = (E[2k][j1], E[2k+1][j1])
    u64 Ea[32], Eb[32];
#pragma unroll
    for (int k = 0; k < 32; ++k) {
        Ea[k] = pack2(__expf(trans[(2 * k) * 66 + j0]),
                      __expf(trans[(2 * k + 1) * 66 + j0]));
        Eb[k] = pack2(__expf(trans[(2 * k) * 66 + j1]),
                      __expf(trans[(2 * k + 1) * 66 + j1]));
    }

    // ---- gold path score (32 lanes of this warp, distinct time steps) ----
    float gold = 0.0f;
    {
        int nk = (seq - lane + 31) >> 5;
#pragma unroll 4
        for (int k = 0; k < nk; ++k) {
            int t  = lane + (k << 5);
            int r  = rb[t];
            int rp = (t == 0) ? 64 : rb[t - 1];
            float g = pb[(size_t)t * 64 + r] + trans[rp * 66 + r];
            if (t == seq - 1) g += trans[r * 66 + 65];
            gold += g;
        }
    }

    // ---- bootstrap: v_1 = exp(alpha_1 - m0), all intra-warp ----
    float a1x = pb[j0] + trans[64 * 66 + j0];
    float a1y = pb[j1] + trans[64 * 66 + j1];
    float m0  = warp_rmax(fmaxf(a1x, a1y));
    float vx  = __expf(a1x - m0);
    float vy  = __expf(a1y - m0);
    int   ks  = 0;

    // prefetch pipeline, depth 3, pairwise (states j0,j1 are adjacent)
    const float2* pb2 = reinterpret_cast<const float2*>(pb) + lane;  // +t*32 per row
    float2 P_cur, pv_a, pv_b, pv_c;
    {
        float2 r1 = pb2[(size_t)min(1, seq - 1) * 32];
        P_cur.x = __expf(r1.x);  P_cur.y = __expf(r1.y);
        pv_a = pb2[(size_t)min(2, seq - 1) * 32];
        pv_b = pb2[(size_t)min(3, seq - 1) * 32];
        pv_c = pb2[(size_t)min(4, seq - 1) * 32];
    }

    u64* epub = reinterpret_cast<u64*>(ebuf[w][0]);   // parity stride = 32 u64
    int par = 0;
    for (int t = 2; t <= seq; ++t) {
        // publish v_{t-1} pair (natural STS.64), sync this warp only
        epub[par * 32 + lane] = pack2(vx, vy);
        __syncwarp();

        // prefetch rotate AFTER the sync (R13 finding)
        float Pnx = __expf(pv_a.x);
        float Pny = __expf(pv_a.y);
        pv_a = pv_b;
        pv_b = pv_c;
        int tn = t + 3;
        int tc = tn < seq - 1 ? tn : seq - 1;
        pv_c = pb2[(size_t)tc * 32];

        // s_j = sum_i v_i E[i][j] for j0 and j1 — 16x LDS.128 + 64x FFMA2
        const ulonglong2* evv =
            reinterpret_cast<const ulonglong2*>(ebuf[w][par]);
        u64 A0 = 0ull, A1 = 0ull, B0 = 0ull, B1 = 0ull;
        ulonglong2 q0 = evv[0];

        // uniform exact power-of-two scale from v_{t-1}[0] (lo of first pair)
        float v0 = __uint_as_float((unsigned int)q0.x);
        int   ex = (__float_as_int(v0) >> 23) - 127;
        float rs = __int_as_float((127 - ex) << 23);
        float fx = P_cur.x * rs;
        float fy = P_cur.y * rs;

        A0 = ffma2(q0.x, Ea[0], A0);  B0 = ffma2(q0.x, Eb[0], B0);
        A1 = ffma2(q0.y, Ea[1], A1);  B1 = ffma2(q0.y, Eb[1], B1);
#pragma unroll
        for (int k = 1; k < 16; ++k) {
            ulonglong2 q = evv[k];
            A0 = ffma2(q.x, Ea[2 * k],     A0);
            B0 = ffma2(q.x, Eb[2 * k],     B0);
            A1 = ffma2(q.y, Ea[2 * k + 1], A1);
            B1 = ffma2(q.y, Eb[2 * k + 1], B1);
        }

        u64 sA = fadd2(A0, A1);
        u64 sB = fadd2(B0, B1);
        float axl, axh, byl, byh;
        asm("mov.b64 {%0, %1}, %2;" : "=f"(axl), "=f"(axh) : "l"(sA));
        asm("mov.b64 {%0, %1}, %2;" : "=f"(byl), "=f"(byh) : "l"(sB));
        vx = (axl + axh) * fx;
        vy = (byl + byh) * fy;
        ks += ex;

        P_cur.x = Pnx;
        P_cur.y = Pny;
        par ^= 1;
    }

    // ---- logZ and per-batch loss (all intra-warp) ----
    float tEx = __expf(trans[j0 * 66 + 65]);
    float tEy = __expf(trans[j1 * 66 + 65]);
    float sw  = warp_rsum(vx * tEx + vy * tEy);
    float gs  = warp_rsum(gold);
    if (lane == 0 && wr) {
        double loss = (double)m0 + 0.6931471805599453 * (double)ks
                    + (double)__logf(sw) - (double)gs;
        g_partial[b] = loss;
    }
    __syncthreads();
    if (tid == 0) {
        __threadfence();
        int c = atomicAdd(&g_count, 1);
        s_last = (c == (int)gridDim.x - 1) ? 1 : 0;
    }
    __syncthreads();

    // ---- last CTA: deterministic fixed-order final reduction ----
    if (s_last) {
        __threadfence();
        double s = 0.0;
        for (int i = tid; i < B; i += 64) s += g_partial[i];
        red[tid] = s;
        __syncthreads();
#pragma unroll
        for (int wd = 32; wd > 0; wd >>= 1) {
            if (tid < wd) red[tid] += red[tid + wd];
            __syncthreads();
        }
        for (int i = tid; i < out_size; i += 64)
            out[i] = (i == 0) ? (float)red[0] : 0.0f;
        if (tid == 0) g_count = 0;   // reset for next graph replay
    }
}

extern "C" void kernel_launch(void* const* d_in, const int* in_sizes, int n_in,
                              void* d_out, int out_size)
{
    // Identify inputs by element count (robust to metadata ordering):
    //   trans = 66*66 = 4356, pred = largest, seq_len = smallest, ref = rest.
    int it = -1;
    for (int i = 0; i < n_in; ++i)
        if (in_sizes[i] == 66 * 66) { it = i; break; }
    int ip = -1, is = -1;
    for (int i = 0; i < n_in; ++i) {
        if (i == it) continue;
        if (ip < 0 || in_sizes[i] > in_sizes[ip]) ip = i;
        if (is < 0 || in_sizes[i] < in_sizes[is]) is = i;
    }
    int ir = -1;
    for (int i = 0; i < n_in; ++i)
        if (i != it && i != ip && i != is) { ir = i; break; }

    const float* pred  = (const float*)d_in[ip];
    const float* trans = (const float*)d_in[it];
    const int*   ref   = (const int*)d_in[ir];
    const int*   slen  = (const int*)d_in[is];

    const int B = in_sizes[is];
    const int T = in_sizes[ir] / B;

    int grid = (B + 1) / 2;
    crf_kernel<<<grid, 64>>>(pred, trans, ref, slen, (float*)d_out, B, T, out_size);
}

// round 16
// speedup vs baseline: 3.4703x; 3.4703x over previous
#include <cuda_runtime.h>

// CRF negative log-likelihood, L=64 live states, exp-domain recursion.
// R13 topology (measured best): block=64 (one batch, 2 warps), grid=B,
// occ 2 (two independent CTAs interleave per SMSP), per-CTA __syncthreads,
// post-barrier prefetch rotate (defer-blocking window), depth-3 prefetch.
// R15 deltas: scale exponent from the already-loaded q0.x register (no
// scalar LDS), pointer-bump prefetch addressing (no per-step min/IMAD).
//
//   v_t[j]  = (sum_i v_{t-1}[i] * E[i][j]) * exp(pred[b,t-1,j]) * 2^{-ex_t}
//   E[i][j] = exp(trans[i][j]);  ex_t = float exponent of v_{t-1}[0]
//   logZ_b  = m0 + ks*ln2 + log( sum_j v_seq[j] * exp(trans[j][65]) )
//   gold_b  = sum_t pred[b,t,ref_t] + trans[64][ref_0]
//           + sum trans[ref_{t-1}][ref_t] + trans[ref_{seq-1}][65]

__device__ double g_partial[4096];
__device__ int    g_count;   // static zero-init; last CTA resets each run

__device__ __forceinline__ float warp_rmax(float v) {
#pragma unroll
    for (int o = 16; o > 0; o >>= 1)
        v = fmaxf(v, __shfl_xor_sync(0xffffffffu, v, o));
    return v;
}
__device__ __forceinline__ float warp_rsum(float v) {
#pragma unroll
    for (int o = 16; o > 0; o >>= 1)
        v += __shfl_xor_sync(0xffffffffu, v, o);
    return v;
}

typedef unsigned long long u64;
__device__ __forceinline__ u64 ffma2(u64 a, u64 b, u64 c) {
    u64 d;
    asm("fma.rn.f32x2 %0, %1, %2, %3;" : "=l"(d) : "l"(a), "l"(b), "l"(c));
    return d;
}
__device__ __forceinline__ u64 fadd2(u64 a, u64 b) {
    u64 d;
    asm("add.rn.f32x2 %0, %1, %2;" : "=l"(d) : "l"(a), "l"(b));
    return d;
}
__device__ __forceinline__ u64 pack2(float lo, float hi) {
    u64 d;
    asm("mov.b64 %0, {%1, %2};" : "=l"(d) : "f"(lo), "f"(hi));
    return d;
}

__global__ void __launch_bounds__(64, 2)
crf_kernel(const float* __restrict__ pred,
           const float* __restrict__ trans,
           const int*   __restrict__ ref,
           const int*   __restrict__ slen,
           float* __restrict__ out,
           int B, int T, int out_size)
{
    __shared__ float4 e[2][16];     // double-buffered v vector (64 floats)
    __shared__ float  fin[4];
    __shared__ double red[64];
    __shared__ int    s_last;

    const int j    = threadIdx.x;   // state column, 0..63
    const int wih  = j >> 5;
    const int lane = j & 31;
    const int b    = blockIdx.x;    // grid = B exactly

    const float* pb  = pred + (size_t)b * T * 64;
    const int*   rb  = ref  + (size_t)b * T;
    const int    seq = slen[b];

    // E column j as 32 packed f32x2 pairs
    u64 E2[32];
#pragma unroll
    for (int p = 0; p < 32; ++p)
        E2[p] = pack2(__expf(trans[(2 * p) * 66 + j]),
                      __expf(trans[(2 * p + 1) * 66 + j]));

    // ---- gold path score (parallel over time) ----
    float gold = 0.0f;
    {
        int nk = (seq - j + 63) >> 6;
#pragma unroll 4
        for (int k = 0; k < nk; ++k) {
            int t  = j + (k << 6);
            int r  = rb[t];
            int rp = (t == 0) ? 64 : rb[t - 1];
            float g = pb[(size_t)t * 64 + r] + trans[rp * 66 + r];
            if (t == seq - 1) g += trans[r * 66 + 65];
            gold += g;
        }
    }

    // ---- bootstrap: v_1 = exp(alpha_1 - m0) ----
    float alpha1 = pb[j] + trans[64 * 66 + j];
    float wm = warp_rmax(alpha1);
    if (lane == 0) fin[wih] = wm;
    __syncthreads();
    float m0 = fmaxf(fin[0], fin[1]);
    float v  = __expf(alpha1 - m0);
    int   ks = 0;

    // prefetch pipeline, depth 3: P_cur = exp(pred row t-1) consumed at t;
    // pv_a/pv_b/pv_c hold rows t, t+1, t+2. pv_c refilled via a predicated
    // pointer bump (pc clamped at row seq-1) — no per-step min/IMAD.
    float P_cur = __expf(pb[(size_t)min(1, seq - 1) * 64 + j]);
    float pv_a  = pb[(size_t)min(2, seq - 1) * 64 + j];
    float pv_b  = pb[(size_t)min(3, seq - 1) * 64 + j];
    float pv_c  = pb[(size_t)min(4, seq - 1) * 64 + j];
    const float* pend = pb + (size_t)(seq - 1) * 64 + j;           // last row
    const float* pc   = pb + (size_t)min(5, seq - 1) * 64 + j;     // row t+3 at t=2

    int par = 0;
    for (int t = 2; t <= seq; ++t) {
        // publish v_{t-1}, arrive at the barrier immediately
        reinterpret_cast<float*>(e[par])[j] = v;
        __syncthreads();

        // prefetch rotate AFTER the bar: defer-blocking lets these LDG/MUFU
        // execute inside the barrier-wait window (first blocked op is the
        // vector LDS of e[par] below).
        float Pn = __expf(pv_a);
        pv_a = pv_b;
        pv_b = pv_c;
        pv_c = *pc;
        pc += (pc < pend) ? 64 : 0;

        // s_j = sum_i v_i * E[i][j]  — 16x LDS.128 + 32x FFMA2
        const ulonglong2* evv = reinterpret_cast<const ulonglong2*>(e[par]);
        u64 a0 = 0ull, a1 = 0ull, a2 = 0ull, a3 = 0ull;
        ulonglong2 q0 = evv[0], q1 = evv[1], q2 = evv[2], q3 = evv[3];
        ulonglong2 q4 = evv[4], q5 = evv[5], q6 = evv[6], q7 = evv[7];

        // uniform exact power-of-two scale straight from the loaded register
        // (low float of q0 = v_{t-1}[0]) — no scalar LDS on the chain head.
        float v0 = __uint_as_float((unsigned int)q0.x);
        int   ex = (__float_as_int(v0) >> 23) - 127;
        float factor = P_cur * __int_as_float((127 - ex) << 23);
        ks += ex;

        a0 = ffma2(q0.x, E2[0],  a0);
        a1 = ffma2(q0.y, E2[1],  a1);
        a2 = ffma2(q1.x, E2[2],  a2);
        a3 = ffma2(q1.y, E2[3],  a3);
        a0 = ffma2(q2.x, E2[4],  a0);
        a1 = ffma2(q2.y, E2[5],  a1);
        a2 = ffma2(q3.x, E2[6],  a2);
        a3 = ffma2(q3.y, E2[7],  a3);
        a0 = ffma2(q4.x, E2[8],  a0);
        a1 = ffma2(q4.y, E2[9],  a1);
        a2 = ffma2(q5.x, E2[10], a2);
        a3 = ffma2(q5.y, E2[11], a3);
        a0 = ffma2(q6.x, E2[12], a0);
        a1 = ffma2(q6.y, E2[13], a1);
        a2 = ffma2(q7.x, E2[14], a2);
        a3 = ffma2(q7.y, E2[15], a3);
        ulonglong2 r0 = evv[8],  r1 = evv[9],  r2 = evv[10], r3 = evv[11];
        ulonglong2 r4 = evv[12], r5 = evv[13], r6 = evv[14], r7 = evv[15];
        a0 = ffma2(r0.x, E2[16], a0);
        a1 = ffma2(r0.y, E2[17], a1);
        a2 = ffma2(r1.x, E2[18], a2);
        a3 = ffma2(r1.y, E2[19], a3);
        a0 = ffma2(r2.x, E2[20], a0);
        a1 = ffma2(r2.y, E2[21], a1);
        a2 = ffma2(r3.x, E2[22], a2);
        a3 = ffma2(r3.y, E2[23], a3);
        a0 = ffma2(r4.x, E2[24], a0);
        a1 = ffma2(r4.y, E2[25], a1);
        a2 = ffma2(r5.x, E2[26], a2);
        a3 = ffma2(r5.y, E2[27], a3);
        a0 = ffma2(r6.x, E2[28], a0);
        a1 = ffma2(r6.y, E2[29], a1);
        a2 = ffma2(r7.x, E2[30], a2);
        a3 = ffma2(r7.y, E2[31], a3);

        u64 s2 = fadd2(fadd2(a0, a2), fadd2(a1, a3));
        float slo, shi;
        asm("mov.b64 {%0, %1}, %2;" : "=f"(slo), "=f"(shi) : "l"(s2));
        v = (slo + shi) * factor;

        P_cur = Pn;
        par ^= 1;
    }

    // ---- logZ and per-batch loss ----
    float tE = __expf(trans[j * 66 + 65]);
    float sw = warp_rsum(v * tE);
    float gs = warp_rsum(gold);
    if (lane == 0) { fin[wih] = sw; fin[2 + wih] = gs; }
    __syncthreads();
    if (j == 0) {
        double loss = (double)m0 + 0.6931471805599453 * (double)ks
                    + (double)__logf(fin[0] + fin[1])
                    - (double)(fin[2] + fin[3]);
        g_partial[b] = loss;
        __threadfence();
        int c = atomicAdd(&g_count, 1);
        s_last = (c == (int)gridDim.x - 1) ? 1 : 0;
    }
    __syncthreads();

    // ---- last CTA: deterministic fixed-order final reduction ----
    if (s_last) {
        __threadfence();
        double s = 0.0;
        for (int i = j; i < B; i += 64) s += g_partial[i];
        red[j] = s;
        __syncthreads();
#pragma unroll
        for (int wd = 32; wd > 0; wd >>= 1) {
            if (j < wd) red[j] += red[j + wd];
            __syncthreads();
        }
        for (int i = j; i < out_size; i += 64)
            out[i] = (i == 0) ? (float)red[0] : 0.0f;
        if (j == 0) g_count = 0;   // reset for next graph replay
    }
}

extern "C" void kernel_launch(void* const* d_in, const int* in_sizes, int n_in,
                              void* d_out, int out_size)
{
    // Identify inputs by element count (robust to metadata ordering):
    //   trans = 66*66 = 4356, pred = largest, seq_len = smallest, ref = rest.
    int it = -1;
    for (int i = 0; i < n_in; ++i)
        if (in_sizes[i] == 66 * 66) { it = i; break; }
    int ip = -1, is = -1;
    for (int i = 0; i < n_in; ++i) {
        if (i == it) continue;
        if (ip < 0 || in_sizes[i] > in_sizes[ip]) ip = i;
        if (is < 0 || in_sizes[i] < in_sizes[is]) is = i;
    }
    int ir = -1;
    for (int i = 0; i < n_in; ++i)
        if (i != it && i != ip && i != is) { ir = i; break; }

    const float* pred  = (const float*)d_in[ip];
    const float* trans = (const float*)d_in[it];
    const int*   ref   = (const int*)d_in[ir];
    const int*   slen  = (const int*)d_in[is];

    const int B = in_sizes[is];
    const int T = in_sizes[ir] / B;

    crf_kernel<<<B, 64>>>(pred, trans, ref, slen, (float*)d_out, B, T, out_size);
}